// round 3
// baseline (speedup 1.0000x reference)
#include <cuda_runtime.h>
#include <cuda_bf16.h>
#include <stdint.h>

#define DI __device__ __forceinline__

// Scratch (device globals: allocation-free contract)
__device__ __nv_bfloat16 g_fk[4096 * 512];    // gated K halves [B*NK, 512]
__device__ __nv_bfloat16 g_fvT[512 * 4096];   // gated V halves, TRANSPOSED [512, B*NK]
__device__ float         g_ao[4096 * 512];    // attention out, heads 0..7
__device__ float         g_cvec[1024];        // bo + v_sum @ Wo[:,512:].T
__device__ int           g_mask_u8;

DI uint32_t pack_bf16(float a, float b) {
    __nv_bfloat162 t = __floats2bfloat162_rn(a, b);
    return *reinterpret_cast<uint32_t*>(&t);
}
DI uint32_t f2tf32(float f) {
    uint32_t r;
    asm("cvt.rna.tf32.f32 %0, %1;" : "=r"(r) : "f"(f));
    return r;
}
DI void mma_bf16(float* c, uint32_t a0, uint32_t a1, uint32_t a2, uint32_t a3,
                 uint32_t b0, uint32_t b1) {
    asm volatile(
        "mma.sync.aligned.m16n8k16.row.col.f32.bf16.bf16.f32 "
        "{%0,%1,%2,%3}, {%4,%5,%6,%7}, {%8,%9}, {%0,%1,%2,%3};\n"
        : "+f"(c[0]), "+f"(c[1]), "+f"(c[2]), "+f"(c[3])
        : "r"(a0), "r"(a1), "r"(a2), "r"(a3), "r"(b0), "r"(b1));
}
DI void mma_tf32(float* c, uint32_t a0, uint32_t a1, uint32_t a2, uint32_t a3,
                 uint32_t b0, uint32_t b1) {
    asm volatile(
        "mma.sync.aligned.m16n8k8.row.col.f32.tf32.tf32.f32 "
        "{%0,%1,%2,%3}, {%4,%5,%6,%7}, {%8,%9}, {%0,%1,%2,%3};\n"
        : "+f"(c[0]), "+f"(c[1]), "+f"(c[2]), "+f"(c[3])
        : "r"(a0), "r"(a1), "r"(a2), "r"(a3), "r"(b0), "r"(b1));
}
// exp2 without MUFU: magic-number round + deg-4 poly + exponent injection.
// Max rel err ~4e-5 over f in [-0.5,0.5]; clamps to 2^-126 for -inf-ish args.
DI float exp2fast(float y) {
    y = fmaxf(y, -126.0f);
    float t = y + 12582912.0f;            // 1.5*2^23: round-to-nearest-int
    int   i = __float_as_int(t);
    float f = y - (t - 12582912.0f);
    float p = 1.0f + f * (0.69314718f + f * (0.24022651f +
                      f * (0.05550411f + f * 0.00961813f)));
    return p * __int_as_float((i + (127 - 4194304)) << 23);
}

// ---------------- mask dtype detection (u8 vs 32-bit) ----------------
__global__ void detect_kernel(const uint32_t* __restrict__ m) {
    __shared__ int f;
    if (threadIdx.x == 0) f = 0;
    __syncthreads();
    int loc = 0;
    for (int i = threadIdx.x; i < 262144; i += 256) {   // scan first 1 MB
        uint32_t w = m[i];
        if ((w & 0xFFFFFF00u) != 0u && w != 0x3F800000u) loc = 1;
    }
    if (loc) f = 1;                                     // benign race
    __syncthreads();
    if (threadIdx.x == 0) g_mask_u8 = f;
}

// ---------------- cvec: bo + v_sum @ Wo[:,512:1024].T (warp per output) -----
__global__ void cvec_kernel(const float* __restrict__ vsum,
                            const float* __restrict__ Wo,
                            const float* __restrict__ bo) {
    int w = (blockIdx.x * blockDim.x + threadIdx.x) >> 5;
    int lane = threadIdx.x & 31;
    if (w >= 1024) return;
    float s = 0.0f;
    for (int j = lane; j < 512; j += 32)
        s += vsum[j] * Wo[(size_t)w * 1024 + 512 + j];
    #pragma unroll
    for (int o = 16; o; o >>= 1) s += __shfl_xor_sync(~0u, s, o);
    if (lane == 0) g_cvec[w] = s + bo[w];
}

// ---------------- gating GEMM + sigmoid: [4096,1024]@[1024,512]^T -----------
// which==0 -> g_fk row-major; which==1 -> g_fvT transposed
__global__ __launch_bounds__(256) void gate_kernel(
    const float* __restrict__ X, const float* __restrict__ W,
    const float* __restrict__ b1, const float* __restrict__ b2, int which) {
    __shared__ __nv_bfloat16 Xs[128][72];
    __shared__ __nv_bfloat16 Ws[64][72];
    const int tid = threadIdx.x, warp = tid >> 5, lane = tid & 31;
    const int gid = lane >> 2, t4 = lane & 3;
    const int m0 = blockIdx.x * 128, n0 = blockIdx.y * 64;
    float acc[8][4] = {};

    for (int kc = 0; kc < 16; kc++) {
        const int k0 = kc * 64;
        __syncthreads();
        #pragma unroll
        for (int i = 0; i < 8; i++) {
            int idx = tid + i * 256, r = idx >> 4, c4 = (idx & 15) * 4;
            float4 v = *reinterpret_cast<const float4*>(X + (size_t)(m0 + r) * 1024 + k0 + c4);
            *reinterpret_cast<uint2*>(&Xs[r][c4]) =
                make_uint2(pack_bf16(v.x, v.y), pack_bf16(v.z, v.w));
        }
        #pragma unroll
        for (int i = 0; i < 4; i++) {
            int idx = tid + i * 256, r = idx >> 4, c4 = (idx & 15) * 4;
            float4 v = *reinterpret_cast<const float4*>(W + (size_t)(n0 + r) * 1024 + k0 + c4);
            *reinterpret_cast<uint2*>(&Ws[r][c4]) =
                make_uint2(pack_bf16(v.x, v.y), pack_bf16(v.z, v.w));
        }
        __syncthreads();
        const int rowa = warp * 16 + gid;
        const uint32_t* X0 = reinterpret_cast<const uint32_t*>(&Xs[rowa][0]);
        const uint32_t* X1 = reinterpret_cast<const uint32_t*>(&Xs[rowa + 8][0]);
        #pragma unroll
        for (int ks = 0; ks < 4; ks++) {
            uint32_t a0 = X0[ks * 8 + t4], a1 = X1[ks * 8 + t4];
            uint32_t a2 = X0[ks * 8 + t4 + 4], a3 = X1[ks * 8 + t4 + 4];
            #pragma unroll
            for (int j = 0; j < 8; j++) {
                const uint32_t* Wr = reinterpret_cast<const uint32_t*>(&Ws[j * 8 + gid][0]);
                mma_bf16(acc[j], a0, a1, a2, a3, Wr[ks * 8 + t4], Wr[ks * 8 + t4 + 4]);
            }
        }
    }
    const int rowa = warp * 16 + gid;
    #pragma unroll
    for (int j = 0; j < 8; j++) {
        int col = n0 + j * 8 + t4 * 2;
        float bb0 = b1[col] + b2[col], bb1 = b1[col + 1] + b2[col + 1];
        float s0 = 1.0f / (1.0f + __expf(-(acc[j][0] + bb0)));
        float s1 = 1.0f / (1.0f + __expf(-(acc[j][1] + bb1)));
        float s2 = 1.0f / (1.0f + __expf(-(acc[j][2] + bb0)));
        float s3 = 1.0f / (1.0f + __expf(-(acc[j][3] + bb1)));
        if (which == 0) {
            *reinterpret_cast<uint32_t*>(&g_fk[(size_t)(m0 + rowa) * 512 + col]) = pack_bf16(s0, s1);
            *reinterpret_cast<uint32_t*>(&g_fk[(size_t)(m0 + rowa + 8) * 512 + col]) = pack_bf16(s2, s3);
        } else {
            g_fvT[(size_t)col * 4096 + m0 + rowa]           = __float2bfloat16(s0);
            g_fvT[(size_t)(col + 1) * 4096 + m0 + rowa]     = __float2bfloat16(s1);
            g_fvT[(size_t)col * 4096 + m0 + rowa + 8]       = __float2bfloat16(s2);
            g_fvT[(size_t)(col + 1) * 4096 + m0 + rowa + 8] = __float2bfloat16(s3);
        }
    }
}

// ---------------- flash attention, heads 0..7 -------------------------------
__global__ __launch_bounds__(256, 2) void attn_kernel(
    const float* __restrict__ Q, const float* __restrict__ Wt,
    const uint8_t* __restrict__ Mask) {
    __shared__ __nv_bfloat16 q_s[128][72];
    __shared__ __nv_bfloat16 k_s[64][72];
    __shared__ __nv_bfloat16 v_t[64][72];   // [dv][key]
    const int tid = threadIdx.x, warp = tid >> 5, lane = tid & 31;
    const int gid = lane >> 2, t4 = lane & 3;
    const int q0 = blockIdx.x * 128, h = blockIdx.y, b = blockIdx.z;
    const int mu8 = g_mask_u8;

    // stage Q, folding 0.125 * log2(e) (log2-domain softmax)
    #pragma unroll
    for (int i = 0; i < 8; i++) {
        int idx = tid + i * 256, r = idx >> 4, c4 = (idx & 15) * 4;
        float4 v = *reinterpret_cast<const float4*>(
            Q + (size_t)(b * 2048 + q0 + r) * 1024 + h * 64 + c4);
        const float sc = 0.18033688f;
        *reinterpret_cast<uint2*>(&q_s[r][c4]) =
            make_uint2(pack_bf16(v.x * sc, v.y * sc), pack_bf16(v.z * sc, v.w * sc));
    }
    __syncthreads();
    const int rowa = warp * 16 + gid;
    uint32_t qa[4][4];
    {
        const uint32_t* Q0 = reinterpret_cast<const uint32_t*>(&q_s[rowa][0]);
        const uint32_t* Q1 = reinterpret_cast<const uint32_t*>(&q_s[rowa + 8][0]);
        #pragma unroll
        for (int ks = 0; ks < 4; ks++) {
            qa[ks][0] = Q0[ks * 8 + t4];     qa[ks][1] = Q1[ks * 8 + t4];
            qa[ks][2] = Q0[ks * 8 + t4 + 4]; qa[ks][3] = Q1[ks * 8 + t4 + 4];
        }
    }
    float acc[8][4] = {};
    float mrow0 = -1e30f, mrow1 = -1e30f, lrow0 = 0.0f, lrow1 = 0.0f;
    const size_t wbase = (size_t)(b * 16 + h) * 2048 * 2048;
    const int r0 = q0 + rowa, r1 = r0 + 8;

    for (int kt = 0; kt < 32; kt++) {
        const int k0 = kt * 64;
        __syncthreads();
        #pragma unroll
        for (int i = 0; i < 8; i++) {
            int idx = tid + i * 256, r = idx >> 5, c = (idx & 31) * 2;
            *reinterpret_cast<uint32_t*>(&k_s[r][c]) =
                *reinterpret_cast<const uint32_t*>(&g_fk[(size_t)(b * 2048 + k0 + r) * 512 + h * 64 + c]);
            *reinterpret_cast<uint32_t*>(&v_t[r][c]) =
                *reinterpret_cast<const uint32_t*>(&g_fvT[(size_t)(h * 64 + r) * 4096 + b * 2048 + k0 + c]);
        }
        __syncthreads();

        float s[8][4] = {};
        #pragma unroll
        for (int ks = 0; ks < 4; ks++) {
            #pragma unroll
            for (int j = 0; j < 8; j++) {
                const uint32_t* Kr = reinterpret_cast<const uint32_t*>(&k_s[j * 8 + gid][0]);
                mma_bf16(s[j], qa[ks][0], qa[ks][1], qa[ks][2], qa[ks][3],
                         Kr[ks * 8 + t4], Kr[ks * 8 + t4 + 4]);
            }
        }
        // per-element weights + mask (single-touch: straight from GMEM)
        #pragma unroll
        for (int j = 0; j < 8; j++) {
            int col = k0 + j * 8 + t4 * 2;
            size_t i0 = wbase + (size_t)r0 * 2048 + col;
            size_t i1 = wbase + (size_t)r1 * 2048 + col;
            float2 w0 = *reinterpret_cast<const float2*>(Wt + i0);
            float2 w1 = *reinterpret_cast<const float2*>(Wt + i1);
            int m00, m01, m10, m11;
            if (mu8) {
                uchar2 a  = *reinterpret_cast<const uchar2*>(Mask + i0);
                uchar2 bq = *reinterpret_cast<const uchar2*>(Mask + i1);
                m00 = a.x; m01 = a.y; m10 = bq.x; m11 = bq.y;
            } else {
                const uint32_t* M32 = reinterpret_cast<const uint32_t*>(Mask);
                uint2 a  = *reinterpret_cast<const uint2*>(M32 + i0);
                uint2 bq = *reinterpret_cast<const uint2*>(M32 + i1);
                m00 = (a.x != 0u); m01 = (a.y != 0u); m10 = (bq.x != 0u); m11 = (bq.y != 0u);
            }
            s[j][0] = m00 ? -1e30f : s[j][0] * w0.x;
            s[j][1] = m01 ? -1e30f : s[j][1] * w0.y;
            s[j][2] = m10 ? -1e30f : s[j][2] * w1.x;
            s[j][3] = m11 ? -1e30f : s[j][3] * w1.y;
        }
        // online softmax (log2 domain)
        float tm0 = -1e30f, tm1 = -1e30f;
        #pragma unroll
        for (int j = 0; j < 8; j++) {
            tm0 = fmaxf(tm0, fmaxf(s[j][0], s[j][1]));
            tm1 = fmaxf(tm1, fmaxf(s[j][2], s[j][3]));
        }
        tm0 = fmaxf(tm0, __shfl_xor_sync(~0u, tm0, 1));
        tm0 = fmaxf(tm0, __shfl_xor_sync(~0u, tm0, 2));
        tm1 = fmaxf(tm1, __shfl_xor_sync(~0u, tm1, 1));
        tm1 = fmaxf(tm1, __shfl_xor_sync(~0u, tm1, 2));
        float mn0 = fmaxf(mrow0, tm0), mn1 = fmaxf(mrow1, tm1);
        float sc0 = exp2fast(mrow0 - mn0), sc1 = exp2fast(mrow1 - mn1);
        float ts0 = 0.0f, ts1 = 0.0f;
        #pragma unroll
        for (int j = 0; j < 8; j++) {
            s[j][0] = exp2fast(s[j][0] - mn0);
            s[j][1] = exp2fast(s[j][1] - mn0);
            s[j][2] = exp2fast(s[j][2] - mn1);
            s[j][3] = exp2fast(s[j][3] - mn1);
            ts0 += s[j][0] + s[j][1];
            ts1 += s[j][2] + s[j][3];
            acc[j][0] *= sc0; acc[j][1] *= sc0;
            acc[j][2] *= sc1; acc[j][3] *= sc1;
        }
        ts0 += __shfl_xor_sync(~0u, ts0, 1); ts0 += __shfl_xor_sync(~0u, ts0, 2);
        ts1 += __shfl_xor_sync(~0u, ts1, 1); ts1 += __shfl_xor_sync(~0u, ts1, 2);
        lrow0 = lrow0 * sc0 + ts0; lrow1 = lrow1 * sc1 + ts1;
        mrow0 = mn0; mrow1 = mn1;
        // P @ V  (P frags straight from registers; V^T gives contiguous B frags)
        #pragma unroll
        for (int kk = 0; kk < 4; kk++) {
            uint32_t a0 = pack_bf16(s[2 * kk][0], s[2 * kk][1]);
            uint32_t a1 = pack_bf16(s[2 * kk][2], s[2 * kk][3]);
            uint32_t a2 = pack_bf16(s[2 * kk + 1][0], s[2 * kk + 1][1]);
            uint32_t a3 = pack_bf16(s[2 * kk + 1][2], s[2 * kk + 1][3]);
            #pragma unroll
            for (int jg = 0; jg < 8; jg++) {
                const uint32_t* Vr = reinterpret_cast<const uint32_t*>(&v_t[jg * 8 + gid][0]);
                mma_bf16(acc[jg], a0, a1, a2, a3, Vr[kk * 8 + t4], Vr[kk * 8 + t4 + 4]);
            }
        }
    }
    float inv0 = 1.0f / lrow0, inv1 = 1.0f / lrow1;
    #pragma unroll
    for (int jg = 0; jg < 8; jg++) {
        int col = h * 64 + jg * 8 + t4 * 2;
        *reinterpret_cast<float2*>(&g_ao[(size_t)(b * 2048 + r0) * 512 + col]) =
            make_float2(acc[jg][0] * inv0, acc[jg][1] * inv0);
        *reinterpret_cast<float2*>(&g_ao[(size_t)(b * 2048 + r1) * 512 + col]) =
            make_float2(acc[jg][2] * inv1, acc[jg][3] * inv1);
    }
}

// ---------------- output projection: [4096,512] @ Wo[:, :512]^T + cvec ------
__global__ __launch_bounds__(256) void proj_kernel(const float* __restrict__ Wo,
                                                   float* __restrict__ out) {
    __shared__ uint32_t As[128][36];
    __shared__ uint32_t Bs[64][36];
    const int tid = threadIdx.x, warp = tid >> 5, lane = tid & 31;
    const int gid = lane >> 2, t4 = lane & 3;
    const int m0 = blockIdx.x * 128, n0 = blockIdx.y * 64;
    float acc[8][4] = {};

    for (int kc = 0; kc < 16; kc++) {
        const int k0 = kc * 32;
        __syncthreads();
        #pragma unroll
        for (int i = 0; i < 4; i++) {
            int idx = tid + i * 256, r = idx >> 3, c4 = (idx & 7) * 4;
            float4 v = *reinterpret_cast<const float4*>(g_ao + (size_t)(m0 + r) * 512 + k0 + c4);
            As[r][c4]     = f2tf32(v.x); As[r][c4 + 1] = f2tf32(v.y);
            As[r][c4 + 2] = f2tf32(v.z); As[r][c4 + 3] = f2tf32(v.w);
        }
        #pragma unroll
        for (int i = 0; i < 2; i++) {
            int idx = tid + i * 256, r = idx >> 3, c4 = (idx & 7) * 4;
            float4 v = *reinterpret_cast<const float4*>(Wo + (size_t)(n0 + r) * 1024 + k0 + c4);
            Bs[r][c4]     = f2tf32(v.x); Bs[r][c4 + 1] = f2tf32(v.y);
            Bs[r][c4 + 2] = f2tf32(v.z); Bs[r][c4 + 3] = f2tf32(v.w);
        }
        __syncthreads();
        const int rowa = warp * 16 + gid;
        #pragma unroll
        for (int ks = 0; ks < 4; ks++) {
            uint32_t a0 = As[rowa][ks * 8 + t4],     a1 = As[rowa + 8][ks * 8 + t4];
            uint32_t a2 = As[rowa][ks * 8 + t4 + 4], a3 = As[rowa + 8][ks * 8 + t4 + 4];
            #pragma unroll
            for (int j = 0; j < 8; j++) {
                mma_tf32(acc[j], a0, a1, a2, a3,
                         Bs[j * 8 + gid][ks * 8 + t4], Bs[j * 8 + gid][ks * 8 + t4 + 4]);
            }
        }
    }
    const int rowa = warp * 16 + gid;
    #pragma unroll
    for (int j = 0; j < 8; j++) {
        int col = n0 + j * 8 + t4 * 2;
        float c0 = g_cvec[col], c1 = g_cvec[col + 1];
        *reinterpret_cast<float2*>(out + (size_t)(m0 + rowa) * 1024 + col) =
            make_float2(acc[j][0] + c0, acc[j][1] + c1);
        *reinterpret_cast<float2*>(out + (size_t)(m0 + rowa + 8) * 1024 + col) =
            make_float2(acc[j][2] + c0, acc[j][3] + c1);
    }
}

extern "C" void kernel_launch(void* const* d_in, const int* in_sizes, int n_in,
                              void* d_out, int out_size) {
    (void)in_sizes; (void)n_in; (void)out_size;
    const float*   queries = (const float*)d_in[0];
    const float*   keys    = (const float*)d_in[1];
    const float*   values  = (const float*)d_in[2];
    const uint8_t* mask    = (const uint8_t*)d_in[3];
    const float*   weights = (const float*)d_in[4];
    const float*   Wk      = (const float*)d_in[5];
    const float*   bk      = (const float*)d_in[6];
    const float*   kfb     = (const float*)d_in[7];
    const float*   Wv      = (const float*)d_in[8];
    const float*   bv      = (const float*)d_in[9];
    const float*   vfb     = (const float*)d_in[10];
    // d_in[11] = k_sum: provably irrelevant (heads 8..15 output = v_sum)
    const float*   vsum    = (const float*)d_in[12];
    const float*   Wo      = (const float*)d_in[13];
    const float*   bo      = (const float*)d_in[14];
    float*         out     = (float*)d_out;

    detect_kernel<<<1, 256>>>((const uint32_t*)mask);
    cvec_kernel<<<128, 256>>>(vsum, Wo, bo);
    gate_kernel<<<dim3(32, 8), 256>>>(keys, Wk, bk, kfb, 0);
    gate_kernel<<<dim3(32, 8), 256>>>(values, Wv, bv, vfb, 1);
    attn_kernel<<<dim3(16, 8, 2), 256>>>(queries, weights, mask);
    proj_kernel<<<dim3(32, 16), 256>>>(Wo, out);
}

// round 4
// speedup vs baseline: 1.2983x; 1.2983x over previous
#include <cuda_runtime.h>
#include <cuda_bf16.h>
#include <stdint.h>

#define DI __device__ __forceinline__

// Scratch (device globals: allocation-free contract)
__device__ __nv_bfloat16 g_kb[4096 * 1024];   // keys bf16
__device__ __nv_bfloat16 g_vb[4096 * 1024];   // values bf16
__device__ __nv_bfloat16 g_wkb[512 * 1024];   // Wk_f bf16
__device__ __nv_bfloat16 g_wvb[512 * 1024];   // Wv_f bf16
__device__ __nv_bfloat16 g_fk[4096 * 512];    // gated K halves [B*NK, 512]
__device__ __nv_bfloat16 g_fvT[512 * 4096];   // gated V halves, transposed
__device__ float         g_ao[4096 * 512];    // attention out, heads 0..7
__device__ float         g_cvec[1024];        // bo + v_sum @ Wo[:,512:].T
__device__ int           g_mask_u8;

DI uint32_t pack_bf16(float a, float b) {
    __nv_bfloat162 t = __floats2bfloat162_rn(a, b);
    return *reinterpret_cast<uint32_t*>(&t);
}
DI uint32_t f2tf32(float f) {
    uint32_t r;
    asm("cvt.rna.tf32.f32 %0, %1;" : "=r"(r) : "f"(f));
    return r;
}
DI float ex2(float x) {
    float r;
    asm("ex2.approx.f32 %0, %1;" : "=f"(r) : "f"(x));
    return r;
}
DI void mma_bf16(float* c, uint32_t a0, uint32_t a1, uint32_t a2, uint32_t a3,
                 uint32_t b0, uint32_t b1) {
    asm volatile(
        "mma.sync.aligned.m16n8k16.row.col.f32.bf16.bf16.f32 "
        "{%0,%1,%2,%3}, {%4,%5,%6,%7}, {%8,%9}, {%0,%1,%2,%3};\n"
        : "+f"(c[0]), "+f"(c[1]), "+f"(c[2]), "+f"(c[3])
        : "r"(a0), "r"(a1), "r"(a2), "r"(a3), "r"(b0), "r"(b1));
}
DI void mma_tf32(float* c, uint32_t a0, uint32_t a1, uint32_t a2, uint32_t a3,
                 uint32_t b0, uint32_t b1) {
    asm volatile(
        "mma.sync.aligned.m16n8k8.row.col.f32.tf32.tf32.f32 "
        "{%0,%1,%2,%3}, {%4,%5,%6,%7}, {%8,%9}, {%0,%1,%2,%3};\n"
        : "+f"(c[0]), "+f"(c[1]), "+f"(c[2]), "+f"(c[3])
        : "r"(a0), "r"(a1), "r"(a2), "r"(a3), "r"(b0), "r"(b1));
}
DI void cp_async16(void* smem, const void* gmem) {
    uint32_t s = (uint32_t)__cvta_generic_to_shared(smem);
    asm volatile("cp.async.cg.shared.global [%0], [%1], 16;\n" :: "r"(s), "l"(gmem));
}
DI void cp_commit() { asm volatile("cp.async.commit_group;\n"); }
template <int N> DI void cp_wait() { asm volatile("cp.async.wait_group %0;\n" :: "n"(N)); }

// ---------------- f32 -> bf16 bulk convert ----------------------------------
__global__ void conv_kernel(const float* __restrict__ src,
                            __nv_bfloat16* __restrict__ dst, int n4) {
    int i = blockIdx.x * 256 + threadIdx.x;
    if (i < n4) {
        float4 v = reinterpret_cast<const float4*>(src)[i];
        reinterpret_cast<uint2*>(dst)[i] =
            make_uint2(pack_bf16(v.x, v.y), pack_bf16(v.z, v.w));
    }
}

// ---------------- mask dtype detection (u8 vs 32-bit) -----------------------
__global__ void detect_kernel(const uint32_t* __restrict__ m) {
    __shared__ int f;
    if (threadIdx.x == 0) f = 0;
    __syncthreads();
    int loc = 0;
    for (int i = threadIdx.x; i < 16384; i += 256) {   // scan first 64 KB
        uint32_t w = m[i];
        if ((w & 0xFFFFFF00u) != 0u && w != 0x3F800000u) loc = 1;
    }
    if (loc) f = 1;
    __syncthreads();
    if (threadIdx.x == 0) g_mask_u8 = f;
}

// ---------------- cvec: bo + v_sum @ Wo[:,512:1024].T -----------------------
__global__ void cvec_kernel(const float* __restrict__ vsum,
                            const float* __restrict__ Wo,
                            const float* __restrict__ bo) {
    int w = (blockIdx.x * blockDim.x + threadIdx.x) >> 5;
    int lane = threadIdx.x & 31;
    if (w >= 1024) return;
    float s = 0.0f;
    for (int j = lane; j < 512; j += 32)
        s += vsum[j] * Wo[(size_t)w * 1024 + 512 + j];
    #pragma unroll
    for (int o = 16; o; o >>= 1) s += __shfl_xor_sync(~0u, s, o);
    if (lane == 0) g_cvec[w] = s + bo[w];
}

// ---------------- gating GEMMs (merged, double-buffered) --------------------
// blockIdx.z: 0 -> keys/Wk -> g_fk row-major; 1 -> values/Wv -> g_fvT transposed
__global__ __launch_bounds__(256) void gate_kernel(
    const float* __restrict__ bk, const float* __restrict__ kfb,
    const float* __restrict__ bv, const float* __restrict__ vfb) {
    __shared__ __align__(16) __nv_bfloat16 Xs[2][128 * 40];   // 40 bf16 stride
    __shared__ __align__(16) __nv_bfloat16 Ws[2][64 * 40];
    const int tid = threadIdx.x, warp = tid >> 5, lane = tid & 31;
    const int gid = lane >> 2, t4 = lane & 3;
    const int m0 = blockIdx.x * 128, n0 = blockIdx.y * 64;
    const int which = blockIdx.z;
    const __nv_bfloat16* X = which ? g_vb : g_kb;
    const __nv_bfloat16* W = which ? g_wvb : g_wkb;
    const float* b1 = which ? bv : bk;
    const float* b2 = which ? vfb : kfb;
    float acc[8][4] = {};

    // stage k-chunk [k0, k0+32) into buffer bufi
    auto stage = [&](int bufi, int k0) {
        #pragma unroll
        for (int i = 0; i < 2; i++) {
            int c = tid + i * 256;                 // 512 chunks: 128 rows x 4
            int row = c >> 2, cc = (c & 3) * 16;
            cp_async16((char*)&Xs[bufi][0] + row * 80 + cc,
                       (const char*)(X + (size_t)(m0 + row) * 1024 + k0) + cc);
        }
        {   int row = tid >> 2, cc = (tid & 3) * 16;  // 256 chunks: 64 rows x 4
            cp_async16((char*)&Ws[bufi][0] + row * 80 + cc,
                       (const char*)(W + (size_t)(n0 + row) * 1024 + k0) + cc);
        }
    };

    stage(0, 0); cp_commit();
    const int rowa = warp * 16 + gid;
    for (int kt = 0; kt < 32; kt++) {
        if (kt < 31) { stage((kt + 1) & 1, (kt + 1) * 32); cp_commit(); cp_wait<1>(); }
        else cp_wait<0>();
        __syncthreads();
        const uint32_t* Xw = reinterpret_cast<const uint32_t*>(&Xs[kt & 1][0]);
        const uint32_t* Ww = reinterpret_cast<const uint32_t*>(&Ws[kt & 1][0]);
        #pragma unroll
        for (int ks = 0; ks < 2; ks++) {
            uint32_t a0 = Xw[rowa * 20 + ks * 8 + t4];
            uint32_t a1 = Xw[(rowa + 8) * 20 + ks * 8 + t4];
            uint32_t a2 = Xw[rowa * 20 + ks * 8 + t4 + 4];
            uint32_t a3 = Xw[(rowa + 8) * 20 + ks * 8 + t4 + 4];
            #pragma unroll
            for (int j = 0; j < 8; j++) {
                mma_bf16(acc[j], a0, a1, a2, a3,
                         Ww[(j * 8 + gid) * 20 + ks * 8 + t4],
                         Ww[(j * 8 + gid) * 20 + ks * 8 + t4 + 4]);
            }
        }
        __syncthreads();
    }
    #pragma unroll
    for (int j = 0; j < 8; j++) {
        int col = n0 + j * 8 + t4 * 2;
        float bb0 = b1[col] + b2[col], bb1 = b1[col + 1] + b2[col + 1];
        float s0 = 1.0f / (1.0f + __expf(-(acc[j][0] + bb0)));
        float s1 = 1.0f / (1.0f + __expf(-(acc[j][1] + bb1)));
        float s2 = 1.0f / (1.0f + __expf(-(acc[j][2] + bb0)));
        float s3 = 1.0f / (1.0f + __expf(-(acc[j][3] + bb1)));
        if (which == 0) {
            *reinterpret_cast<uint32_t*>(&g_fk[(size_t)(m0 + rowa) * 512 + col]) = pack_bf16(s0, s1);
            *reinterpret_cast<uint32_t*>(&g_fk[(size_t)(m0 + rowa + 8) * 512 + col]) = pack_bf16(s2, s3);
        } else {
            g_fvT[(size_t)col * 4096 + m0 + rowa]           = __float2bfloat16(s0);
            g_fvT[(size_t)(col + 1) * 4096 + m0 + rowa]     = __float2bfloat16(s1);
            g_fvT[(size_t)col * 4096 + m0 + rowa + 8]       = __float2bfloat16(s2);
            g_fvT[(size_t)(col + 1) * 4096 + m0 + rowa + 8] = __float2bfloat16(s3);
        }
    }
}

// ---------------- flash attention, heads 0..7 (no-max softmax, MUFU ex2) ----
__global__ __launch_bounds__(256, 2) void attn_kernel(
    const float* __restrict__ Q, const float* __restrict__ Wt,
    const uint8_t* __restrict__ Mask) {
    __shared__ __align__(16) __nv_bfloat16 kbuf[2][64 * 88];   // 88 bf16 stride
    __shared__ __align__(16) __nv_bfloat16 vbuf[2][64 * 88];
    const int tid = threadIdx.x, warp = tid >> 5, lane = tid & 31;
    const int gid = lane >> 2, t4 = lane & 3;
    const int q0 = blockIdx.x * 128, h = blockIdx.y, b = blockIdx.z;
    const int mu8 = g_mask_u8;
    const int bq = b * 2048;
    const int rowa = warp * 16 + gid;
    const int r0 = q0 + rowa, r1 = r0 + 8;

    // Q fragments straight from GMEM (fold 1/8 * log2(e))
    uint32_t qa[4][4];
    {
        const float sc = 0.18033688f;
        #pragma unroll
        for (int ks = 0; ks < 4; ks++) {
            const float* p0 = Q + (size_t)(bq + r0) * 1024 + h * 64 + ks * 16 + t4 * 2;
            const float* p1 = Q + (size_t)(bq + r1) * 1024 + h * 64 + ks * 16 + t4 * 2;
            float2 x0 = __ldcs(reinterpret_cast<const float2*>(p0));
            float2 x1 = __ldcs(reinterpret_cast<const float2*>(p1));
            float2 x2 = __ldcs(reinterpret_cast<const float2*>(p0 + 8));
            float2 x3 = __ldcs(reinterpret_cast<const float2*>(p1 + 8));
            qa[ks][0] = pack_bf16(x0.x * sc, x0.y * sc);
            qa[ks][1] = pack_bf16(x1.x * sc, x1.y * sc);
            qa[ks][2] = pack_bf16(x2.x * sc, x2.y * sc);
            qa[ks][3] = pack_bf16(x3.x * sc, x3.y * sc);
        }
    }

    auto stage = [&](int bufi, int k0) {
        #pragma unroll
        for (int i = 0; i < 2; i++) {
            int c = tid + i * 256;                 // 512 chunks: 64 rows x 8
            int row = c >> 3, cc = (c & 7) * 16;
            cp_async16((char*)&kbuf[bufi][0] + row * 176 + cc,
                       (const char*)(g_fk + (size_t)(bq + k0 + row) * 512 + h * 64) + cc);
            cp_async16((char*)&vbuf[bufi][0] + row * 176 + cc,
                       (const char*)(g_fvT + (size_t)(h * 64 + row) * 4096 + bq + k0) + cc);
        }
    };

    float acc[8][4] = {};
    float lrow0 = 0.0f, lrow1 = 0.0f;
    const size_t wbase = (size_t)(b * 16 + h) * 2048 * 2048;
    const float* wp0 = Wt + wbase + (size_t)r0 * 2048;
    const float* wp1 = Wt + wbase + (size_t)r1 * 2048;
    const size_t mb0 = wbase + (size_t)r0 * 2048;
    const size_t mb1 = wbase + (size_t)r1 * 2048;

    stage(0, 0); cp_commit();
    for (int kt = 0; kt < 32; kt++) {
        const int k0 = kt * 64;
        if (kt < 31) { stage((kt + 1) & 1, k0 + 64); cp_commit(); cp_wait<1>(); }
        else cp_wait<0>();
        __syncthreads();
        const uint32_t* Kw = reinterpret_cast<const uint32_t*>(&kbuf[kt & 1][0]);
        const uint32_t* Vw = reinterpret_cast<const uint32_t*>(&vbuf[kt & 1][0]);

        float s[8][4] = {};
        #pragma unroll
        for (int ks = 0; ks < 4; ks++) {
            #pragma unroll
            for (int j = 0; j < 8; j++) {
                mma_bf16(s[j], qa[ks][0], qa[ks][1], qa[ks][2], qa[ks][3],
                         Kw[(j * 8 + gid) * 44 + ks * 8 + t4],
                         Kw[(j * 8 + gid) * 44 + ks * 8 + t4 + 4]);
            }
        }
        // weights * mask * exp2 (no max-shift; scores provably bounded)
        #pragma unroll
        for (int j = 0; j < 8; j++) {
            int col = k0 + j * 8 + t4 * 2;
            float2 w0 = __ldcs(reinterpret_cast<const float2*>(wp0 + col));
            float2 w1 = __ldcs(reinterpret_cast<const float2*>(wp1 + col));
            float p00 = ex2(s[j][0] * w0.x);
            float p01 = ex2(s[j][1] * w0.y);
            float p10 = ex2(s[j][2] * w1.x);
            float p11 = ex2(s[j][3] * w1.y);
            if (mu8) {
                unsigned short a = __ldcs(reinterpret_cast<const unsigned short*>(Mask + mb0 + col));
                unsigned short c = __ldcs(reinterpret_cast<const unsigned short*>(Mask + mb1 + col));
                p00 = (a & 0xFF) ? 0.0f : p00;
                p01 = (a >> 8)   ? 0.0f : p01;
                p10 = (c & 0xFF) ? 0.0f : p10;
                p11 = (c >> 8)   ? 0.0f : p11;
            } else {
                const uint32_t* M32 = reinterpret_cast<const uint32_t*>(Mask);
                uint2 a = __ldcs(reinterpret_cast<const uint2*>(M32 + mb0 + col));
                uint2 c = __ldcs(reinterpret_cast<const uint2*>(M32 + mb1 + col));
                p00 = a.x ? 0.0f : p00;
                p01 = a.y ? 0.0f : p01;
                p10 = c.x ? 0.0f : p10;
                p11 = c.y ? 0.0f : p11;
            }
            lrow0 += p00 + p01;
            lrow1 += p10 + p11;
            s[j][0] = p00; s[j][1] = p01; s[j][2] = p10; s[j][3] = p11;
        }
        // P @ V
        #pragma unroll
        for (int kk = 0; kk < 4; kk++) {
            uint32_t a0 = pack_bf16(s[2 * kk][0], s[2 * kk][1]);
            uint32_t a1 = pack_bf16(s[2 * kk][2], s[2 * kk][3]);
            uint32_t a2 = pack_bf16(s[2 * kk + 1][0], s[2 * kk + 1][1]);
            uint32_t a3 = pack_bf16(s[2 * kk + 1][2], s[2 * kk + 1][3]);
            #pragma unroll
            for (int jg = 0; jg < 8; jg++) {
                mma_bf16(acc[jg], a0, a1, a2, a3,
                         Vw[(jg * 8 + gid) * 44 + kk * 8 + t4],
                         Vw[(jg * 8 + gid) * 44 + kk * 8 + t4 + 4]);
            }
        }
        __syncthreads();
    }
    // deferred cross-lane l reduction
    lrow0 += __shfl_xor_sync(~0u, lrow0, 1); lrow0 += __shfl_xor_sync(~0u, lrow0, 2);
    lrow1 += __shfl_xor_sync(~0u, lrow1, 1); lrow1 += __shfl_xor_sync(~0u, lrow1, 2);
    float inv0 = 1.0f / lrow0, inv1 = 1.0f / lrow1;
    #pragma unroll
    for (int jg = 0; jg < 8; jg++) {
        int col = h * 64 + jg * 8 + t4 * 2;
        *reinterpret_cast<float2*>(&g_ao[(size_t)(bq + r0) * 512 + col]) =
            make_float2(acc[jg][0] * inv0, acc[jg][1] * inv0);
        *reinterpret_cast<float2*>(&g_ao[(size_t)(bq + r1) * 512 + col]) =
            make_float2(acc[jg][2] * inv1, acc[jg][3] * inv1);
    }
}

// ---------------- output projection (tf32, double-buffered) -----------------
__global__ __launch_bounds__(256) void proj_kernel(const float* __restrict__ Wo,
                                                   float* __restrict__ out) {
    __shared__ __align__(16) float As[2][64 * 36];
    __shared__ __align__(16) float Bs[2][64 * 36];
    const int tid = threadIdx.x, warp = tid >> 5, lane = tid & 31;
    const int gid = lane >> 2, t4 = lane & 3;
    const int wr = warp >> 1, wc = warp & 1;
    const int m0 = blockIdx.x * 64, n0 = blockIdx.y * 64;
    float acc[4][4] = {};

    auto stage = [&](int bufi, int k0) {
        #pragma unroll
        for (int i = 0; i < 2; i++) {
            int c = tid + i * 256;                 // 512 chunks: 64 rows x 8
            int row = c >> 3, cc = (c & 7) * 16;
            cp_async16((char*)&As[bufi][0] + row * 144 + cc,
                       (const char*)(g_ao + (size_t)(m0 + row) * 512 + k0) + cc);
            cp_async16((char*)&Bs[bufi][0] + row * 144 + cc,
                       (const char*)(Wo + (size_t)(n0 + row) * 1024 + k0) + cc);
        }
    };

    stage(0, 0); cp_commit();
    const int rowa = wr * 16 + gid;
    for (int kt = 0; kt < 16; kt++) {
        if (kt < 15) { stage((kt + 1) & 1, (kt + 1) * 32); cp_commit(); cp_wait<1>(); }
        else cp_wait<0>();
        __syncthreads();
        const float* Af = &As[kt & 1][0];
        const float* Bf = &Bs[kt & 1][0];
        #pragma unroll
        for (int ks = 0; ks < 4; ks++) {
            uint32_t a0 = f2tf32(Af[rowa * 36 + ks * 8 + t4]);
            uint32_t a1 = f2tf32(Af[(rowa + 8) * 36 + ks * 8 + t4]);
            uint32_t a2 = f2tf32(Af[rowa * 36 + ks * 8 + t4 + 4]);
            uint32_t a3 = f2tf32(Af[(rowa + 8) * 36 + ks * 8 + t4 + 4]);
            #pragma unroll
            for (int j = 0; j < 4; j++) {
                int nrow = wc * 32 + j * 8 + gid;
                mma_tf32(acc[j], a0, a1, a2, a3,
                         f2tf32(Bf[nrow * 36 + ks * 8 + t4]),
                         f2tf32(Bf[nrow * 36 + ks * 8 + t4 + 4]));
            }
        }
        __syncthreads();
    }
    #pragma unroll
    for (int j = 0; j < 4; j++) {
        int col = n0 + wc * 32 + j * 8 + t4 * 2;
        float c0 = g_cvec[col], c1 = g_cvec[col + 1];
        *reinterpret_cast<float2*>(out + (size_t)(m0 + rowa) * 1024 + col) =
            make_float2(acc[j][0] + c0, acc[j][1] + c1);
        *reinterpret_cast<float2*>(out + (size_t)(m0 + rowa + 8) * 1024 + col) =
            make_float2(acc[j][2] + c0, acc[j][3] + c1);
    }
}

extern "C" void kernel_launch(void* const* d_in, const int* in_sizes, int n_in,
                              void* d_out, int out_size) {
    (void)in_sizes; (void)n_in; (void)out_size;
    const float*   queries = (const float*)d_in[0];
    const float*   keys    = (const float*)d_in[1];
    const float*   values  = (const float*)d_in[2];
    const uint8_t* mask    = (const uint8_t*)d_in[3];
    const float*   weights = (const float*)d_in[4];
    const float*   Wk      = (const float*)d_in[5];
    const float*   bk      = (const float*)d_in[6];
    const float*   kfb     = (const float*)d_in[7];
    const float*   Wv      = (const float*)d_in[8];
    const float*   bv      = (const float*)d_in[9];
    const float*   vfb     = (const float*)d_in[10];
    // d_in[11] = k_sum: provably irrelevant (heads 8..15 output = v_sum)
    const float*   vsum    = (const float*)d_in[12];
    const float*   Wo      = (const float*)d_in[13];
    const float*   bo      = (const float*)d_in[14];
    float*         out     = (float*)d_out;

    __nv_bfloat16 *kb, *vb, *wkb, *wvb;
    cudaGetSymbolAddress((void**)&kb,  g_kb);
    cudaGetSymbolAddress((void**)&vb,  g_vb);
    cudaGetSymbolAddress((void**)&wkb, g_wkb);
    cudaGetSymbolAddress((void**)&wvb, g_wvb);

    conv_kernel<<<4096, 256>>>(keys,   kb,  1048576);
    conv_kernel<<<4096, 256>>>(values, vb,  1048576);
    conv_kernel<<<512,  256>>>(Wk,     wkb, 131072);
    conv_kernel<<<512,  256>>>(Wv,     wvb, 131072);
    detect_kernel<<<1, 256>>>((const uint32_t*)mask);
    cvec_kernel<<<128, 256>>>(vsum, Wo, bo);
    gate_kernel<<<dim3(32, 8, 2), 256>>>(bk, kfb, bv, vfb);
    attn_kernel<<<dim3(16, 8, 2), 256>>>(queries, weights, mask);
    proj_kernel<<<dim3(64, 16), 256>>>(Wo, out);
}

// round 5
// speedup vs baseline: 1.3368x; 1.0297x over previous
#include <cuda_runtime.h>
#include <cuda_bf16.h>
#include <stdint.h>

#define DI __device__ __forceinline__

// Scratch (device globals: allocation-free contract)
__device__ __nv_bfloat16 g_kb[4096 * 1024];   // keys bf16
__device__ __nv_bfloat16 g_vb[4096 * 1024];   // values bf16
__device__ __nv_bfloat16 g_wkb[512 * 1024];   // Wk_f bf16
__device__ __nv_bfloat16 g_wvb[512 * 1024];   // Wv_f bf16
__device__ __align__(16) float g_wot[1024 * 512];  // Wo[:, :512] tf32-rounded
__device__ __nv_bfloat16 g_fk[4096 * 512];    // gated K halves [B*NK, 512]
__device__ __nv_bfloat16 g_fvT[512 * 4096];   // gated V halves, transposed
__device__ __align__(16) float g_ao[4096 * 512];   // attention out (tf32-rounded)
__device__ float         g_cvec[1024];        // bo + v_sum @ Wo[:,512:].T
__device__ __align__(16) uint32_t g_mbits[16 * 2048 * 64];  // mask bitset, heads 0..7
__device__ int           g_mask_u8;

DI uint32_t pack_bf16(float a, float b) {
    __nv_bfloat162 t = __floats2bfloat162_rn(a, b);
    return *reinterpret_cast<uint32_t*>(&t);
}
DI uint32_t f2tf32(float f) {
    uint32_t r;
    asm("cvt.rna.tf32.f32 %0, %1;" : "=r"(r) : "f"(f));
    return r;
}
DI float ex2(float x) {
    float r;
    asm("ex2.approx.f32 %0, %1;" : "=f"(r) : "f"(x));
    return r;
}
DI void mma_bf16(float* c, uint32_t a0, uint32_t a1, uint32_t a2, uint32_t a3,
                 uint32_t b0, uint32_t b1) {
    asm volatile(
        "mma.sync.aligned.m16n8k16.row.col.f32.bf16.bf16.f32 "
        "{%0,%1,%2,%3}, {%4,%5,%6,%7}, {%8,%9}, {%0,%1,%2,%3};\n"
        : "+f"(c[0]), "+f"(c[1]), "+f"(c[2]), "+f"(c[3])
        : "r"(a0), "r"(a1), "r"(a2), "r"(a3), "r"(b0), "r"(b1));
}
DI void mma_tf32(float* c, uint32_t a0, uint32_t a1, uint32_t a2, uint32_t a3,
                 uint32_t b0, uint32_t b1) {
    asm volatile(
        "mma.sync.aligned.m16n8k8.row.col.f32.tf32.tf32.f32 "
        "{%0,%1,%2,%3}, {%4,%5,%6,%7}, {%8,%9}, {%0,%1,%2,%3};\n"
        : "+f"(c[0]), "+f"(c[1]), "+f"(c[2]), "+f"(c[3])
        : "r"(a0), "r"(a1), "r"(a2), "r"(a3), "r"(b0), "r"(b1));
}
DI void cp_async16(void* smem, const void* gmem) {
    uint32_t s = (uint32_t)__cvta_generic_to_shared(smem);
    asm volatile("cp.async.cg.shared.global [%0], [%1], 16;\n" :: "r"(s), "l"(gmem));
}
DI void cp_commit() { asm volatile("cp.async.commit_group;\n"); }
template <int N> DI void cp_wait() { asm volatile("cp.async.wait_group %0;\n" :: "n"(N)); }

// ---------------- merged converts: keys/values/Wk/Wv -> bf16, Wo -> tf32 ----
__global__ void conv_all(const float* __restrict__ keys, const float* __restrict__ values,
                         const float* __restrict__ Wk, const float* __restrict__ Wv,
                         const float* __restrict__ Wo) {
    int i = blockIdx.x * 256 + threadIdx.x;
    if (i < 1048576) {
        float4 v = reinterpret_cast<const float4*>(keys)[i];
        reinterpret_cast<uint2*>(g_kb)[i] = make_uint2(pack_bf16(v.x, v.y), pack_bf16(v.z, v.w));
    } else if (i < 2097152) {
        int j = i - 1048576;
        float4 v = reinterpret_cast<const float4*>(values)[j];
        reinterpret_cast<uint2*>(g_vb)[j] = make_uint2(pack_bf16(v.x, v.y), pack_bf16(v.z, v.w));
    } else if (i < 2228224) {
        int j = i - 2097152;
        float4 v = reinterpret_cast<const float4*>(Wk)[j];
        reinterpret_cast<uint2*>(g_wkb)[j] = make_uint2(pack_bf16(v.x, v.y), pack_bf16(v.z, v.w));
    } else if (i < 2359296) {
        int j = i - 2228224;
        float4 v = reinterpret_cast<const float4*>(Wv)[j];
        reinterpret_cast<uint2*>(g_wvb)[j] = make_uint2(pack_bf16(v.x, v.y), pack_bf16(v.z, v.w));
    } else if (i < 2490368) {
        int j = i - 2359296;             // 131072 chunks over Wo[:, :512]
        int row = j >> 7, c4 = (j & 127) * 4;
        float4 v = *reinterpret_cast<const float4*>(Wo + (size_t)row * 1024 + c4);
        float4 r;
        r.x = __uint_as_float(f2tf32(v.x)); r.y = __uint_as_float(f2tf32(v.y));
        r.z = __uint_as_float(f2tf32(v.z)); r.w = __uint_as_float(f2tf32(v.w));
        *reinterpret_cast<float4*>(&g_wot[(size_t)row * 512 + c4]) = r;
    }
}

// ---------------- mask dtype detection (u8 vs 32-bit) -----------------------
__global__ void detect_kernel(const uint32_t* __restrict__ m) {
    __shared__ int f;
    if (threadIdx.x == 0) f = 0;
    __syncthreads();
    int loc = 0;
    for (int i = threadIdx.x; i < 16384; i += 256) {   // scan first 64 KB
        uint32_t w = m[i];
        if ((w & 0xFFFFFF00u) != 0u && w != 0x3F800000u) loc = 1;
    }
    if (loc) f = 1;
    __syncthreads();
    if (threadIdx.x == 0) g_mask_u8 = f;
}

// ---------------- cvec: bo + v_sum @ Wo[:,512:1024].T -----------------------
__global__ void cvec_kernel(const float* __restrict__ vsum,
                            const float* __restrict__ Wo,
                            const float* __restrict__ bo) {
    int w = (blockIdx.x * blockDim.x + threadIdx.x) >> 5;
    int lane = threadIdx.x & 31;
    if (w >= 1024) return;
    float s = 0.0f;
    for (int j = lane; j < 512; j += 32)
        s += vsum[j] * Wo[(size_t)w * 1024 + 512 + j];
    #pragma unroll
    for (int o = 16; o; o >>= 1) s += __shfl_xor_sync(~0u, s, o);
    if (lane == 0) g_cvec[w] = s + bo[w];
}

// ---------------- mask -> bitset repack (heads 0..7 only) -------------------
__global__ void repack_kernel(const uint8_t* __restrict__ Mask) {
    const int warp = threadIdx.x >> 5, lane = threadIdx.x & 31;
    const int bh = blockIdx.y;                 // 0..15 -> (b, h<8)
    const int row = blockIdx.x * 8 + warp;
    const int b = bh >> 3, h = bh & 7;
    const size_t base = ((size_t)(b * 16 + h) * 2048 + row) * 2048;
    uint32_t* dst = g_mbits + ((size_t)bh * 2048 + row) * 64;
    if (g_mask_u8) {
        #pragma unroll 4
        for (int w = 0; w < 64; w++) {
            int v = Mask[base + w * 32 + lane] != 0;
            uint32_t bits = __ballot_sync(~0u, v);
            if (lane == 0) dst[w] = bits;
        }
    } else {
        const uint32_t* M32 = reinterpret_cast<const uint32_t*>(Mask);
        #pragma unroll 4
        for (int w = 0; w < 64; w++) {
            int v = M32[base + w * 32 + lane] != 0u;   // covers i32 and f32
            uint32_t bits = __ballot_sync(~0u, v);
            if (lane == 0) dst[w] = bits;
        }
    }
}

// ---------------- gating GEMMs (merged, double-buffered) --------------------
__global__ __launch_bounds__(256) void gate_kernel(
    const float* __restrict__ bk, const float* __restrict__ kfb,
    const float* __restrict__ bv, const float* __restrict__ vfb) {
    __shared__ __align__(16) __nv_bfloat16 Xs[2][128 * 40];
    __shared__ __align__(16) __nv_bfloat16 Ws[2][64 * 40];
    const int tid = threadIdx.x, warp = tid >> 5, lane = tid & 31;
    const int gid = lane >> 2, t4 = lane & 3;
    const int m0 = blockIdx.x * 128, n0 = blockIdx.y * 64;
    const int which = blockIdx.z;
    const __nv_bfloat16* X = which ? g_vb : g_kb;
    const __nv_bfloat16* W = which ? g_wvb : g_wkb;
    const float* b1 = which ? bv : bk;
    const float* b2 = which ? vfb : kfb;
    float acc[8][4] = {};

    auto stage = [&](int bufi, int k0) {
        #pragma unroll
        for (int i = 0; i < 2; i++) {
            int c = tid + i * 256;
            int row = c >> 2, cc = (c & 3) * 16;
            cp_async16((char*)&Xs[bufi][0] + row * 80 + cc,
                       (const char*)(X + (size_t)(m0 + row) * 1024 + k0) + cc);
        }
        {   int row = tid >> 2, cc = (tid & 3) * 16;
            cp_async16((char*)&Ws[bufi][0] + row * 80 + cc,
                       (const char*)(W + (size_t)(n0 + row) * 1024 + k0) + cc);
        }
    };

    stage(0, 0); cp_commit();
    const int rowa = warp * 16 + gid;
    for (int kt = 0; kt < 32; kt++) {
        if (kt < 31) { stage((kt + 1) & 1, (kt + 1) * 32); cp_commit(); cp_wait<1>(); }
        else cp_wait<0>();
        __syncthreads();
        const uint32_t* Xw = reinterpret_cast<const uint32_t*>(&Xs[kt & 1][0]);
        const uint32_t* Ww = reinterpret_cast<const uint32_t*>(&Ws[kt & 1][0]);
        #pragma unroll
        for (int ks = 0; ks < 2; ks++) {
            uint32_t a0 = Xw[rowa * 20 + ks * 8 + t4];
            uint32_t a1 = Xw[(rowa + 8) * 20 + ks * 8 + t4];
            uint32_t a2 = Xw[rowa * 20 + ks * 8 + t4 + 4];
            uint32_t a3 = Xw[(rowa + 8) * 20 + ks * 8 + t4 + 4];
            #pragma unroll
            for (int j = 0; j < 8; j++) {
                mma_bf16(acc[j], a0, a1, a2, a3,
                         Ww[(j * 8 + gid) * 20 + ks * 8 + t4],
                         Ww[(j * 8 + gid) * 20 + ks * 8 + t4 + 4]);
            }
        }
        __syncthreads();
    }
    #pragma unroll
    for (int j = 0; j < 8; j++) {
        int col = n0 + j * 8 + t4 * 2;
        float bb0 = b1[col] + b2[col], bb1 = b1[col + 1] + b2[col + 1];
        float s0 = 1.0f / (1.0f + __expf(-(acc[j][0] + bb0)));
        float s1 = 1.0f / (1.0f + __expf(-(acc[j][1] + bb1)));
        float s2 = 1.0f / (1.0f + __expf(-(acc[j][2] + bb0)));
        float s3 = 1.0f / (1.0f + __expf(-(acc[j][3] + bb1)));
        if (which == 0) {
            *reinterpret_cast<uint32_t*>(&g_fk[(size_t)(m0 + rowa) * 512 + col]) = pack_bf16(s0, s1);
            *reinterpret_cast<uint32_t*>(&g_fk[(size_t)(m0 + rowa + 8) * 512 + col]) = pack_bf16(s2, s3);
        } else {
            g_fvT[(size_t)col * 4096 + m0 + rowa]           = __float2bfloat16(s0);
            g_fvT[(size_t)(col + 1) * 4096 + m0 + rowa]     = __float2bfloat16(s1);
            g_fvT[(size_t)col * 4096 + m0 + rowa + 8]       = __float2bfloat16(s2);
            g_fvT[(size_t)(col + 1) * 4096 + m0 + rowa + 8] = __float2bfloat16(s3);
        }
    }
}

// ---------------- flash attention, heads 0..7 -------------------------------
// no-max softmax (scores bounded), MUFU ex2, weight prefetch, bitset mask,
// fused per-pair softmax+PV to cut live registers.
__global__ __launch_bounds__(256, 2) void attn_kernel(
    const float* __restrict__ Q, const float* __restrict__ Wt) {
    __shared__ __align__(16) __nv_bfloat16 kbuf[2][64 * 88];
    __shared__ __align__(16) __nv_bfloat16 vbuf[2][64 * 88];
    const int tid = threadIdx.x, warp = tid >> 5, lane = tid & 31;
    const int gid = lane >> 2, t4 = lane & 3;
    const int q0 = blockIdx.x * 128, h = blockIdx.y, b = blockIdx.z;
    const int bq = b * 2048;
    const int rowa = warp * 16 + gid;
    const int r0 = q0 + rowa, r1 = r0 + 8;

    uint32_t qa[4][4];
    {
        const float sc = 0.18033688f;   // (1/8) * log2(e)
        #pragma unroll
        for (int ks = 0; ks < 4; ks++) {
            const float* p0 = Q + (size_t)(bq + r0) * 1024 + h * 64 + ks * 16 + t4 * 2;
            const float* p1 = Q + (size_t)(bq + r1) * 1024 + h * 64 + ks * 16 + t4 * 2;
            float2 x0 = __ldcs(reinterpret_cast<const float2*>(p0));
            float2 x1 = __ldcs(reinterpret_cast<const float2*>(p1));
            float2 x2 = __ldcs(reinterpret_cast<const float2*>(p0 + 8));
            float2 x3 = __ldcs(reinterpret_cast<const float2*>(p1 + 8));
            qa[ks][0] = pack_bf16(x0.x * sc, x0.y * sc);
            qa[ks][1] = pack_bf16(x1.x * sc, x1.y * sc);
            qa[ks][2] = pack_bf16(x2.x * sc, x2.y * sc);
            qa[ks][3] = pack_bf16(x3.x * sc, x3.y * sc);
        }
    }

    auto stage = [&](int bufi, int k0) {
        #pragma unroll
        for (int i = 0; i < 2; i++) {
            int c = tid + i * 256;
            int row = c >> 3, cc = (c & 7) * 16;
            cp_async16((char*)&kbuf[bufi][0] + row * 176 + cc,
                       (const char*)(g_fk + (size_t)(bq + k0 + row) * 512 + h * 64) + cc);
            cp_async16((char*)&vbuf[bufi][0] + row * 176 + cc,
                       (const char*)(g_fvT + (size_t)(h * 64 + row) * 4096 + bq + k0) + cc);
        }
    };

    float acc[8][4] = {};
    float lrow0 = 0.0f, lrow1 = 0.0f;
    const size_t wbase = (size_t)(b * 16 + h) * 2048 * 2048;
    const float* wp0 = Wt + wbase + (size_t)r0 * 2048;
    const float* wp1 = Wt + wbase + (size_t)r1 * 2048;
    const uint32_t* mp0 = g_mbits + ((size_t)(b * 8 + h) * 2048 + r0) * 64;
    const uint32_t* mp1 = g_mbits + ((size_t)(b * 8 + h) * 2048 + r1) * 64;

    stage(0, 0); cp_commit();
    for (int kt = 0; kt < 32; kt++) {
        const int k0 = kt * 64;
        if (kt < 31) { stage((kt + 1) & 1, k0 + 64); cp_commit(); cp_wait<1>(); }
        else cp_wait<0>();
        // prefetch weights + mask bits for this tile (independent of smem —
        // LDGs fly while the sync + QK HMMA chain executes)
        float2 w0r[8], w1r[8];
        #pragma unroll
        for (int j = 0; j < 8; j++) {
            w0r[j] = __ldcs(reinterpret_cast<const float2*>(wp0 + k0 + j * 8 + t4 * 2));
            w1r[j] = __ldcs(reinterpret_cast<const float2*>(wp1 + k0 + j * 8 + t4 * 2));
        }
        uint2 mw0 = __ldcs(reinterpret_cast<const uint2*>(mp0 + kt * 2));
        uint2 mw1 = __ldcs(reinterpret_cast<const uint2*>(mp1 + kt * 2));
        __syncthreads();
        const uint32_t* Kw = reinterpret_cast<const uint32_t*>(&kbuf[kt & 1][0]);
        const uint32_t* Vw = reinterpret_cast<const uint32_t*>(&vbuf[kt & 1][0]);

        #pragma unroll
        for (int kk = 0; kk < 4; kk++) {
            const int j0 = 2 * kk, j1 = 2 * kk + 1;
            float s0[4] = {}, s1[4] = {};
            #pragma unroll
            for (int ks = 0; ks < 4; ks++)
                mma_bf16(s0, qa[ks][0], qa[ks][1], qa[ks][2], qa[ks][3],
                         Kw[(j0 * 8 + gid) * 44 + ks * 8 + t4],
                         Kw[(j0 * 8 + gid) * 44 + ks * 8 + t4 + 4]);
            #pragma unroll
            for (int ks = 0; ks < 4; ks++)
                mma_bf16(s1, qa[ks][0], qa[ks][1], qa[ks][2], qa[ks][3],
                         Kw[(j1 * 8 + gid) * 44 + ks * 8 + t4],
                         Kw[(j1 * 8 + gid) * 44 + ks * 8 + t4 + 4]);
            const int bit0 = (j0 * 8 + t4 * 2) & 31, bit1 = (j1 * 8 + t4 * 2) & 31;
            const uint32_t sel00 = (j0 < 4) ? mw0.x : mw0.y;
            const uint32_t sel01 = (j0 < 4) ? mw1.x : mw1.y;
            const uint32_t sel10 = (j1 < 4) ? mw0.x : mw0.y;
            const uint32_t sel11 = (j1 < 4) ? mw1.x : mw1.y;
            float p00 = ex2(s0[0] * w0r[j0].x), p01 = ex2(s0[1] * w0r[j0].y);
            float p02 = ex2(s0[2] * w1r[j0].x), p03 = ex2(s0[3] * w1r[j0].y);
            float p10 = ex2(s1[0] * w0r[j1].x), p11 = ex2(s1[1] * w0r[j1].y);
            float p12 = ex2(s1[2] * w1r[j1].x), p13 = ex2(s1[3] * w1r[j1].y);
            p00 = ((sel00 >> bit0) & 1)       ? 0.0f : p00;
            p01 = ((sel00 >> (bit0 + 1)) & 1) ? 0.0f : p01;
            p02 = ((sel01 >> bit0) & 1)       ? 0.0f : p02;
            p03 = ((sel01 >> (bit0 + 1)) & 1) ? 0.0f : p03;
            p10 = ((sel10 >> bit1) & 1)       ? 0.0f : p10;
            p11 = ((sel10 >> (bit1 + 1)) & 1) ? 0.0f : p11;
            p12 = ((sel11 >> bit1) & 1)       ? 0.0f : p12;
            p13 = ((sel11 >> (bit1 + 1)) & 1) ? 0.0f : p13;
            lrow0 += p00 + p01 + p10 + p11;
            lrow1 += p02 + p03 + p12 + p13;
            uint32_t a0 = pack_bf16(p00, p01), a1 = pack_bf16(p02, p03);
            uint32_t a2 = pack_bf16(p10, p11), a3 = pack_bf16(p12, p13);
            #pragma unroll
            for (int jg = 0; jg < 8; jg++)
                mma_bf16(acc[jg], a0, a1, a2, a3,
                         Vw[(jg * 8 + gid) * 44 + kk * 8 + t4],
                         Vw[(jg * 8 + gid) * 44 + kk * 8 + t4 + 4]);
        }
        __syncthreads();
    }
    lrow0 += __shfl_xor_sync(~0u, lrow0, 1); lrow0 += __shfl_xor_sync(~0u, lrow0, 2);
    lrow1 += __shfl_xor_sync(~0u, lrow1, 1); lrow1 += __shfl_xor_sync(~0u, lrow1, 2);
    float inv0 = 1.0f / lrow0, inv1 = 1.0f / lrow1;
    #pragma unroll
    for (int jg = 0; jg < 8; jg++) {
        int col = h * 64 + jg * 8 + t4 * 2;
        *reinterpret_cast<float2*>(&g_ao[(size_t)(bq + r0) * 512 + col]) =
            make_float2(__uint_as_float(f2tf32(acc[jg][0] * inv0)),
                        __uint_as_float(f2tf32(acc[jg][1] * inv0)));
        *reinterpret_cast<float2*>(&g_ao[(size_t)(bq + r1) * 512 + col]) =
            make_float2(__uint_as_float(f2tf32(acc[jg][2] * inv1)),
                        __uint_as_float(f2tf32(acc[jg][3] * inv1)));
    }
}

// ---------------- output projection (tf32, zero-cvt, double-buffered) -------
__global__ __launch_bounds__(256) void proj_kernel(float* __restrict__ out) {
    __shared__ __align__(16) float As[2][64 * 36];
    __shared__ __align__(16) float Bs[2][64 * 36];
    const int tid = threadIdx.x, warp = tid >> 5, lane = tid & 31;
    const int gid = lane >> 2, t4 = lane & 3;
    const int wr = warp >> 1, wc = warp & 1;
    const int m0 = blockIdx.x * 64, n0 = blockIdx.y * 64;
    float acc[4][4] = {};

    auto stage = [&](int bufi, int k0) {
        #pragma unroll
        for (int i = 0; i < 2; i++) {
            int c = tid + i * 256;
            int row = c >> 3, cc = (c & 7) * 16;
            cp_async16((char*)&As[bufi][0] + row * 144 + cc,
                       (const char*)(g_ao + (size_t)(m0 + row) * 512 + k0) + cc);
            cp_async16((char*)&Bs[bufi][0] + row * 144 + cc,
                       (const char*)(g_wot + (size_t)(n0 + row) * 512 + k0) + cc);
        }
    };

    stage(0, 0); cp_commit();
    const int rowa = wr * 16 + gid;
    for (int kt = 0; kt < 16; kt++) {
        if (kt < 15) { stage((kt + 1) & 1, (kt + 1) * 32); cp_commit(); cp_wait<1>(); }
        else cp_wait<0>();
        __syncthreads();
        const uint32_t* Af = reinterpret_cast<const uint32_t*>(&As[kt & 1][0]);
        const uint32_t* Bf = reinterpret_cast<const uint32_t*>(&Bs[kt & 1][0]);
        #pragma unroll
        for (int ks = 0; ks < 4; ks++) {
            uint32_t a0 = Af[rowa * 36 + ks * 8 + t4];
            uint32_t a1 = Af[(rowa + 8) * 36 + ks * 8 + t4];
            uint32_t a2 = Af[rowa * 36 + ks * 8 + t4 + 4];
            uint32_t a3 = Af[(rowa + 8) * 36 + ks * 8 + t4 + 4];
            #pragma unroll
            for (int j = 0; j < 4; j++) {
                int nrow = wc * 32 + j * 8 + gid;
                mma_tf32(acc[j], a0, a1, a2, a3,
                         Bf[nrow * 36 + ks * 8 + t4], Bf[nrow * 36 + ks * 8 + t4 + 4]);
            }
        }
        __syncthreads();
    }
    #pragma unroll
    for (int j = 0; j < 4; j++) {
        int col = n0 + wc * 32 + j * 8 + t4 * 2;
        float c0 = g_cvec[col], c1 = g_cvec[col + 1];
        *reinterpret_cast<float2*>(out + (size_t)(m0 + rowa) * 1024 + col) =
            make_float2(acc[j][0] + c0, acc[j][1] + c1);
        *reinterpret_cast<float2*>(out + (size_t)(m0 + rowa + 8) * 1024 + col) =
            make_float2(acc[j][2] + c0, acc[j][3] + c1);
    }
}

extern "C" void kernel_launch(void* const* d_in, const int* in_sizes, int n_in,
                              void* d_out, int out_size) {
    (void)in_sizes; (void)n_in; (void)out_size;
    const float*   queries = (const float*)d_in[0];
    const float*   keys    = (const float*)d_in[1];
    const float*   values  = (const float*)d_in[2];
    const uint8_t* mask    = (const uint8_t*)d_in[3];
    const float*   weights = (const float*)d_in[4];
    const float*   Wk      = (const float*)d_in[5];
    const float*   bk      = (const float*)d_in[6];
    const float*   kfb     = (const float*)d_in[7];
    const float*   Wv      = (const float*)d_in[8];
    const float*   bv      = (const float*)d_in[9];
    const float*   vfb     = (const float*)d_in[10];
    // d_in[11] = k_sum: provably irrelevant (heads 8..15 output = v_sum)
    const float*   vsum    = (const float*)d_in[12];
    const float*   Wo      = (const float*)d_in[13];
    const float*   bo      = (const float*)d_in[14];
    float*         out     = (float*)d_out;

    conv_all<<<9728, 256>>>(keys, values, Wk, Wv, Wo);          // launch 0
    detect_kernel<<<1, 256>>>((const uint32_t*)mask);           // launch 1
    cvec_kernel<<<128, 256>>>(vsum, Wo, bo);                    // launch 2
    repack_kernel<<<dim3(256, 16), 256>>>(mask);                // launch 3
    gate_kernel<<<dim3(32, 8, 2), 256>>>(bk, kfb, bv, vfb);     // launch 4
    attn_kernel<<<dim3(16, 8, 2), 256>>>(queries, weights);     // launch 5 (ncu -s 5)
    proj_kernel<<<dim3(64, 16), 256>>>(out);                    // launch 6
}